// round 11
// baseline (speedup 1.0000x reference)
#include <cuda_runtime.h>
#include <cuda_bf16.h>
#include <mma.h>
#include <math.h>

using namespace nvcuda;

#define N_NODES 50000
#define N_EDGES 400000
#define HID 64
#define F_IN 8
#define NL 3

#define K1 132    // e_in padded (130 -> 132)
#define N1 288    // edge hidden padded (260 -> 288)
#define K2P 288   // GEMM2 K padded for wmma chunking (260 -> 288 = 6 x 48)
#define NPAD 50048

#define ETILE 48
#define TPB 256

// ---------------- device scratch (no allocations allowed) ----------------
__device__ float g_feats[N_NODES * HID];
__device__ float g_coors[N_NODES * 3];
__device__ float g_magg[N_NODES * HID];
__device__ float g_cdelta[N_NODES * 3];
__device__ float g_eW1p[NL * K1 * N1];
__device__ float g_eb1p[NL * N1];
__device__ float g_PA[NPAD * N1];
__device__ float g_PB[NPAD * N1];
__device__ float g_zbias[N1];
// W2 split-bf16, chunked: [l][chunk(6)][hi|lo][n(64)][k(48)]
__device__ unsigned short g_W2s[NL * 6 * 2 * 64 * 48];
// W3 split-bf16, chunked: [l][chunk(4)][hi|lo][nloc(64)][k(64)]
__device__ unsigned short g_W3s[NL * 4 * 2 * 64 * 64];

__device__ __forceinline__ float silu_f(float v) {
    return v * __fdividef(1.0f, 1.0f + __expf(-v));
}

typedef unsigned long long u64;
__device__ __forceinline__ u64 packdup(float x) {
    u64 r;
    asm("mov.b64 %0, {%1, %1};" : "=l"(r) : "r"(__float_as_uint(x)));
    return r;
}
__device__ __forceinline__ float2 unpackf2(u64 v) {
    unsigned int lo, hi;
    asm("mov.b64 {%0, %1}, %2;" : "=r"(lo), "=r"(hi) : "l"(v));
    return make_float2(__uint_as_float(lo), __uint_as_float(hi));
}
#define FFMA2(acc, a, w) \
    asm("fma.rn.f32x2 %0, %1, %2, %0;" : "+l"(acc) : "l"(a), "l"(w))

__device__ __forceinline__ void cp16(float* dst_smem, const float* src) {
    unsigned int a = (unsigned int)__cvta_generic_to_shared(dst_smem);
    asm volatile("cp.async.cg.shared.global [%0], [%1], 16;" :: "r"(a), "l"(src));
}
#define CP_COMMIT() asm volatile("cp.async.commit_group;" ::: "memory")
#define CP_WAIT0()  asm volatile("cp.async.wait_group 0;" ::: "memory")

// pack (v0 -> low half, v1 -> high half) as bf16x2
__device__ __forceinline__ unsigned int pack_bf2(float v0, float v1) {
    unsigned int d;
    asm("cvt.rn.bf16x2.f32 %0, %1, %2;" : "=r"(d) : "f"(v1), "f"(v0));
    return d;
}

// ---------------- SIMT GEMM tile (node-side kernels, unchanged) ----------
template<int K, int N, int KC, int AS, int CS, int P, int R, bool ACT, int RPT,
         int TPBT>
__device__ __forceinline__ void gemm_tile(const float* __restrict__ A,
                                          const float* __restrict__ Wg,
                                          const float* __restrict__ Bg,
                                          float* __restrict__ C,
                                          float* __restrict__ Wst)
{
    static_assert(KC % 4 == 0, "KC must be a multiple of 4");
    constexpr int NCHUNK = K / KC;
    constexpr int CHSZ = KC * N;
    constexpr int NLD = CHSZ / 4;
    const int tid = threadIdx.x;
    const int er = tid >> 5;
    const int cc = tid & 31;

    u64 accp[RPT][P];
    float accs[RPT];
#pragma unroll
    for (int i = 0; i < RPT; i++) {
        accs[i] = 0.0f;
#pragma unroll
        for (int p = 0; p < P; p++) accp[i][p] = 0ULL;
    }

    for (int i = tid; i < NLD; i += TPBT) cp16(Wst + 4 * i, Wg + 4 * i);
    CP_COMMIT();
    CP_WAIT0();
    __syncthreads();

    for (int c = 0; c < NCHUNK; c++) {
        const float* buf = Wst + (c & 1) * CHSZ;
        float* nbuf = Wst + ((c + 1) & 1) * CHSZ;
        if (c + 1 < NCHUNK) {
            const float* src = Wg + (c + 1) * CHSZ;
            for (int i = tid; i < NLD; i += TPBT) cp16(nbuf + 4 * i, src + 4 * i);
            CP_COMMIT();
        }
        const int k0 = c * KC;
#pragma unroll
        for (int kk = 0; kk < KC; kk += 4) {
            u64 w[4][P];
            float ws[4];
#pragma unroll
            for (int k = 0; k < 4; k++) {
#pragma unroll
                for (int p = 0; p < P; p++)
                    w[k][p] = *(const u64*)(buf + (kk + k) * N + 2 * cc + 64 * p);
                if (R) ws[k] = buf[(kk + k) * N + 64 * P + cc];
            }
#pragma unroll
            for (int i = 0; i < RPT; i++) {
                float4 a4 = *(const float4*)(A + (er * RPT + i) * AS + k0 + kk);
                u64 a0 = packdup(a4.x);
                u64 a1 = packdup(a4.y);
                u64 a2 = packdup(a4.z);
                u64 a3 = packdup(a4.w);
#pragma unroll
                for (int p = 0; p < P; p++) {
                    FFMA2(accp[i][p], a0, w[0][p]);
                    FFMA2(accp[i][p], a1, w[1][p]);
                    FFMA2(accp[i][p], a2, w[2][p]);
                    FFMA2(accp[i][p], a3, w[3][p]);
                }
                if (R) {
                    accs[i] = fmaf(a4.x, ws[0], accs[i]);
                    accs[i] = fmaf(a4.y, ws[1], accs[i]);
                    accs[i] = fmaf(a4.z, ws[2], accs[i]);
                    accs[i] = fmaf(a4.w, ws[3], accs[i]);
                }
            }
        }
        if (c + 1 < NCHUNK) CP_WAIT0();
        __syncthreads();
    }

    float2 bv[P];
    float bs = 0.0f;
#pragma unroll
    for (int p = 0; p < P; p++) bv[p] = *(const float2*)(Bg + 2 * cc + 64 * p);
    if (R) bs = Bg[64 * P + cc];
#pragma unroll
    for (int i = 0; i < RPT; i++) {
#pragma unroll
        for (int p = 0; p < P; p++) {
            float2 v = unpackf2(accp[i][p]);
            v.x += bv[p].x;
            v.y += bv[p].y;
            if (ACT) { v.x = silu_f(v.x); v.y = silu_f(v.y); }
            *(float2*)(C + (er * RPT + i) * CS + 2 * cc + 64 * p) = v;
        }
        if (R) {
            float v = accs[i] + bs;
            if (ACT) v = silu_f(v);
            C[(er * RPT + i) * CS + 64 * P + cc] = v;
        }
    }
}

// ---------------- weight prep ----------------
__global__ void __launch_bounds__(256) pad_kernel(const float* __restrict__ eW1,
                                                  const float* __restrict__ eb1,
                                                  const float* __restrict__ eW2,
                                                  const float* __restrict__ cW1)
{
    const int SZ1 = NL * K1 * N1;
    const int SZ2 = NL * N1;
    const int SZW2 = NL * K2P * 64;    // (l,k,n) elements
    const int SZW3 = NL * 64 * 256;    // (l,k,n)
    int i = blockIdx.x * 256 + threadIdx.x;
    if (i < SZ1) {
        int l = i / (K1 * N1);
        int r = (i / N1) % K1;
        int j = i % N1;
        g_eW1p[i] = (r < 130 && j < 260) ? eW1[(l * 130 + r) * 260 + j] : 0.0f;
    } else if (i < SZ1 + SZ2) {
        int ii = i - SZ1;
        int l = ii / N1, j = ii % N1;
        g_eb1p[ii] = (j < 260) ? eb1[l * 260 + j] : 0.0f;
    } else if (i < SZ1 + SZ2 + SZW2) {
        int ii = i - SZ1 - SZ2;
        int l = ii / (K2P * 64);
        int r = ii % (K2P * 64);
        int k = r / 64, n = r % 64;
        float w = (k < 260) ? eW2[(l * 260 + k) * 64 + n] : 0.0f;
        __nv_bfloat16 h = __float2bfloat16(w);
        float hf = __bfloat162float(h);
        __nv_bfloat16 lo = __float2bfloat16(w - hf);
        int c = k / 48, kk = k % 48;
        int base = ((l * 6 + c) * 2) * 3072 + n * 48 + kk;   // 3072 = 64*48
        g_W2s[base] = __bfloat16_as_ushort(h);
        g_W2s[base + 3072] = __bfloat16_as_ushort(lo);
    } else if (i < SZ1 + SZ2 + SZW2 + SZW3) {
        int ii = i - SZ1 - SZ2 - SZW2;
        int l = ii / (64 * 256);
        int r = ii % (64 * 256);
        int k = r / 256, n = r % 256;
        float w = cW1[(l * 64 + k) * 256 + n];
        __nv_bfloat16 h = __float2bfloat16(w);
        float hf = __bfloat162float(h);
        __nv_bfloat16 lo = __float2bfloat16(w - hf);
        int c3 = n >> 6, nloc = n & 63;
        int base = ((l * 4 + c3) * 2) * 4096 + nloc * 64 + k;  // 4096 = 64*64
        g_W3s[base] = __bfloat16_as_ushort(h);
        g_W3s[base + 4096] = __bfloat16_as_ushort(lo);
    }
}

// ---------------- prenode0: embed + coors copy + zeros + PA/PB(l=0) --------
#define PRE0_SMEM_F 13888
__global__ void __launch_bounds__(256, 2) prenode0_kernel(const float* __restrict__ x,
                                                          const float* __restrict__ pos,
                                                          const float* __restrict__ eW,
                                                          const float* __restrict__ eb)
{
    extern __shared__ float sm[];
    float* sF = sm;
    float* Wst = sm + 4096;
    float* sEW = sm + 13312;
    float* sEb = sm + 13824;

    const int tid = threadIdx.x;
    const int n0 = blockIdx.x * 64;

    for (int idx = tid; idx < F_IN * HID; idx += TPB) sEW[idx] = eW[idx];
    if (tid < HID) sEb[tid] = eb[tid];
    if (tid < 192) {
        int n = n0 + tid / 3, d = tid % 3;
        if (n < N_NODES) {
            g_coors[n * 3 + d] = pos[n * 3 + d];
            g_cdelta[n * 3 + d] = 0.0f;
        }
    }
    __syncthreads();

    for (int idx = tid; idx < 64 * 64; idx += TPB) {
        int nl = idx >> 6, k = idx & 63;
        int n = n0 + nl;
        float f = 0.0f;
        if (n < N_NODES) {
            float acc = sEb[k];
#pragma unroll
            for (int j = 0; j < F_IN; j++)
                acc = fmaf(x[n * F_IN + j], sEW[j * HID + k], acc);
            f = acc;
            g_feats[n * HID + k] = f;
            g_magg[n * HID + k] = 0.0f;
        }
        sF[idx] = f;
    }

    const float* W1 = g_eW1p;
    gemm_tile<64, N1, 16, 64, N1, 4, 1, false, 8, TPB>(sF, W1, g_eb1p,
                                                       g_PA + n0 * N1, Wst);
    gemm_tile<64, N1, 16, 64, N1, 4, 1, false, 8, TPB>(sF, W1 + 64 * N1, g_zbias,
                                                       g_PB + n0 * N1, Wst);
}

// ---------------- prenode (layers 1..L-1) ----------------
#define PRE_SMEM_F 13312
__global__ void __launch_bounds__(256, 2) prenode_kernel(int l)
{
    extern __shared__ float sm[];
    float* sF = sm;
    float* Wst = sm + 4096;

    const int tid = threadIdx.x;
    const int n0 = blockIdx.x * 64;

    for (int idx = tid; idx < 64 * 64; idx += TPB) {
        int nl = idx >> 6, k = idx & 63;
        int n = n0 + nl;
        sF[idx] = (n < N_NODES) ? g_feats[n * HID + k] : 0.0f;
    }

    const float* W1 = g_eW1p + l * K1 * N1;
    gemm_tile<64, N1, 16, 64, N1, 4, 1, false, 8, TPB>(sF, W1, g_eb1p + l * N1,
                                                       g_PA + n0 * N1, Wst);
    gemm_tile<64, N1, 16, 64, N1, 4, 1, false, 8, TPB>(sF, W1 + 64 * N1, g_zbias,
                                                       g_PB + n0 * N1, Wst);
}

// ---------------- wmma edge kernel (48 edges/block, 256 thr, 2 CTA/SM) ----
// smem float map:
//   sH1hi  [0, 6912)       bf16 [48][288]   (reused as C3 fp32 [48][272])
//   sH1lo  [6912, 13824)
//   sC2    [13824, 16896)  fp32 [48][64]  (raw D2, then m)
//   sMhi   [16896, 18432)  bf16 [48][64]
//   sMlo   [18432, 19968)
//   sWst   [19968, 26112)  staging: GEMM2 2x12288B / GEMM3 1x16384B
//   sdot   [26112, 26368)
//   scb1   [26368, 26624)
//   seb2   [26624, 26688)
//   sWea   [26688, 26976)
//   sWdist [26976, 27264)
//   srow   [27264, 27312)  int
//   scol   [27312, 27360)  int
//   srel   [27360, 27552)
//   sea    [27552, 27600)
#define EDGE_SMEM_F 27600

__global__ void __launch_bounds__(256, 2) edge_kernel(const int* __restrict__ ei,
                                                      const float* __restrict__ eattr,
                                                      const float* __restrict__ eb2,
                                                      const float* __restrict__ cb1,
                                                      const float* __restrict__ cW2,
                                                      const float* __restrict__ cb2,
                                                      int l)
{
    extern __shared__ float sm[];
    __nv_bfloat16* h1hi = (__nv_bfloat16*)(sm);
    __nv_bfloat16* h1lo = (__nv_bfloat16*)(sm + 6912);
    float* sC3 = sm;                       // reuse after GEMM2
    float* sC2 = sm + 13824;
    __nv_bfloat16* mhi = (__nv_bfloat16*)(sm + 16896);
    __nv_bfloat16* mlo = (__nv_bfloat16*)(sm + 18432);
    float* sWst = sm + 19968;
    float* sdot = sm + 26112;
    float* scb1 = sm + 26368;
    float* seb2 = sm + 26624;
    float* sWea = sm + 26688;
    float* sWdist = sm + 26976;
    int* srow = (int*)(sm + 27264);
    int* scol = (int*)(sm + 27312);
    float* srel = sm + 27360;
    float* sea = sm + 27552;

    const int tid = threadIdx.x;
    const int w = tid >> 5;
    const int e0 = blockIdx.x * ETILE;

    // fire GEMM2 chunk-0 weight staging (12288 B)
    const char* w2base = (const char*)g_W2s + (size_t)l * 6 * 12288;
    for (int i = tid; i < 768; i += TPB)
        cp16((float*)((char*)sWst + i * 16), (const float*)(w2base + i * 16));
    CP_COMMIT();

    // small vectors + edge meta
    sdot[tid] = cW2[l * 256 + tid];
    scb1[tid] = cb1[l * 256 + tid];
    if (tid < 64) seb2[tid] = eb2[l * 64 + tid];
    {
        const float* Wea = g_eW1p + l * K1 * N1 + 128 * N1;
        for (int idx = tid; idx < 2 * N1; idx += TPB) {
            if (idx < N1) sWea[idx] = Wea[idx];
            else sWdist[idx - N1] = Wea[N1 + (idx - N1)];
        }
    }
    if (tid < ETILE) {
        int e = e0 + tid;
        int r = 0, c = 0;
        float ea = 0.0f;
        if (e < N_EDGES) {
            r = ei[e];
            c = ei[N_EDGES + e];
            ea = eattr[e];
        }
        srow[tid] = r;
        scol[tid] = c;
        float rx = g_coors[r * 3 + 0] - g_coors[c * 3 + 0];
        float ry = g_coors[r * 3 + 1] - g_coors[c * 3 + 1];
        float rz = g_coors[r * 3 + 2] - g_coors[c * 3 + 2];
        srel[tid * 4 + 0] = rx;
        srel[tid * 4 + 1] = ry;
        srel[tid * 4 + 2] = rz;
        srel[tid * 4 + 3] = rx * rx + ry * ry + rz * rz;
        sea[tid] = ea;
    }
    __syncthreads();

    // phase A: h1 = silu(PA[row] + PB[col] + ea*Wea + dist*Wdist) -> bf16 hi/lo
    for (int idx = tid; idx < ETILE * 72; idx += TPB) {
        int e = idx / 72, q = idx - e * 72;
        int k = q * 4;
        float v0 = 0.0f, v1 = 0.0f, v2 = 0.0f, v3 = 0.0f;
        if (k < 260) {
            float4 a = *(const float4*)(g_PA + srow[e] * N1 + k);
            float4 b = *(const float4*)(g_PB + scol[e] * N1 + k);
            float4 we = *(const float4*)(sWea + k);
            float4 wd = *(const float4*)(sWdist + k);
            float ea = sea[e], di = srel[e * 4 + 3];
            v0 = silu_f(fmaf(di, wd.x, fmaf(ea, we.x, a.x + b.x)));
            v1 = silu_f(fmaf(di, wd.y, fmaf(ea, we.y, a.y + b.y)));
            v2 = silu_f(fmaf(di, wd.z, fmaf(ea, we.z, a.z + b.z)));
            v3 = silu_f(fmaf(di, wd.w, fmaf(ea, we.w, a.w + b.w)));
        }
        unsigned int p01 = pack_bf2(v0, v1);
        unsigned int p23 = pack_bf2(v2, v3);
        float h0 = __uint_as_float((p01 & 0xFFFFu) << 16);
        float h1 = __uint_as_float(p01 & 0xFFFF0000u);
        float h2 = __uint_as_float((p23 & 0xFFFFu) << 16);
        float h3 = __uint_as_float(p23 & 0xFFFF0000u);
        unsigned int q01 = pack_bf2(v0 - h0, v1 - h1);
        unsigned int q23 = pack_bf2(v2 - h2, v3 - h3);
        int o = (e * K2P + k) >> 1;
        ((unsigned int*)h1hi)[o] = p01;
        ((unsigned int*)h1hi)[o + 1] = p23;
        ((unsigned int*)h1lo)[o] = q01;
        ((unsigned int*)h1lo)[o + 1] = q23;
    }
    CP_WAIT0();
    __syncthreads();

    // ---- GEMM2: C2[48x64] = h1 @ W2 (split bf16, 3 passes) ----
    wmma::fragment<wmma::accumulator, 16, 16, 16, float> c2a, c2b;
    wmma::fill_fragment(c2a, 0.0f);
    wmma::fill_fragment(c2b, 0.0f);
    const int t0 = w;            // tile ids: w and w+8 (w<4)
    const int m0a = (t0 % 3) * 16, n0a = (t0 / 3) * 16;
    const int t1 = w + 8;
    const int m0b = (t1 % 3) * 16, n0b = (t1 / 3) * 16;

    for (int c = 0; c < 6; c++) {
        float* bufc = sWst + (c & 1) * 3072;
        if (c + 1 < 6) {
            const char* src = w2base + (size_t)(c + 1) * 12288;
            char* dst = (char*)(sWst + ((c + 1) & 1) * 3072);
            for (int i = tid; i < 768; i += TPB)
                cp16((float*)(dst + i * 16), (const float*)(src + i * 16));
            CP_COMMIT();
        }
        const __nv_bfloat16* Whi = (const __nv_bfloat16*)bufc;
        const __nv_bfloat16* Wlo = Whi + 3072;
#pragma unroll
        for (int ks = 0; ks < 3; ks++) {
            int k = c * 48 + ks * 16;
            wmma::fragment<wmma::matrix_a, 16, 16, 16, __nv_bfloat16, wmma::row_major> ahi, alo;
            wmma::fragment<wmma::matrix_b, 16, 16, 16, __nv_bfloat16, wmma::col_major> bhi, blo;
            // tile 0
            wmma::load_matrix_sync(ahi, h1hi + m0a * K2P + k, K2P);
            wmma::load_matrix_sync(alo, h1lo + m0a * K2P + k, K2P);
            wmma::load_matrix_sync(bhi, Whi + n0a * 48 + ks * 16, 48);
            wmma::load_matrix_sync(blo, Wlo + n0a * 48 + ks * 16, 48);
            wmma::mma_sync(c2a, ahi, bhi, c2a);
            wmma::mma_sync(c2a, ahi, blo, c2a);
            wmma::mma_sync(c2a, alo, bhi, c2a);
            if (w < 4) {
                wmma::load_matrix_sync(ahi, h1hi + m0b * K2P + k, K2P);
                wmma::load_matrix_sync(alo, h1lo + m0b * K2P + k, K2P);
                wmma::load_matrix_sync(bhi, Whi + n0b * 48 + ks * 16, 48);
                wmma::load_matrix_sync(blo, Wlo + n0b * 48 + ks * 16, 48);
                wmma::mma_sync(c2b, ahi, bhi, c2b);
                wmma::mma_sync(c2b, ahi, blo, c2b);
                wmma::mma_sync(c2b, alo, bhi, c2b);
            }
        }
        if (c + 1 < 6) CP_WAIT0();
        __syncthreads();
    }
    wmma::store_matrix_sync(sC2 + m0a * 64 + n0a, c2a, 64, wmma::mem_row_major);
    if (w < 4)
        wmma::store_matrix_sync(sC2 + m0b * 64 + n0b, c2b, 64, wmma::mem_row_major);
    __syncthreads();

    // m = silu(C2 + eb2): keep fp32 in sC2, write bf16 hi/lo for GEMM3 A
    for (int idx = tid; idx < ETILE * 32; idx += TPB) {
        int e = idx >> 5, j = idx & 31;
        int k = j * 2;
        float v0 = silu_f(sC2[e * 64 + k] + seb2[k]);
        float v1 = silu_f(sC2[e * 64 + k + 1] + seb2[k + 1]);
        sC2[e * 64 + k] = v0;
        sC2[e * 64 + k + 1] = v1;
        unsigned int p = pack_bf2(v0, v1);
        float h0 = __uint_as_float((p & 0xFFFFu) << 16);
        float h1 = __uint_as_float(p & 0xFFFF0000u);
        ((unsigned int*)mhi)[e * 32 + j] = p;
        ((unsigned int*)mlo)[e * 32 + j] = pack_bf2(v0 - h0, v1 - h1);
    }
    __syncthreads();

    // ---- GEMM3: C3[48x256] = m @ W3, 4 n-chunks of 64 ----
    const char* w3base = (const char*)g_W3s + (size_t)l * 4 * 16384;
    for (int c3 = 0; c3 < 4; c3++) {
        const char* src = w3base + (size_t)c3 * 16384;
        for (int i = tid; i < 1024; i += TPB)
            cp16((float*)((char*)sWst + i * 16), (const float*)(src + i * 16));
        CP_COMMIT();
        CP_WAIT0();
        __syncthreads();
        const __nv_bfloat16* Whi = (const __nv_bfloat16*)sWst;
        const __nv_bfloat16* Wlo = Whi + 4096;
#pragma unroll
        for (int jj = 0; jj < 2; jj++) {
            int j = w + jj * 8;
            if (j < 12) {
                int m0 = (j % 3) * 16;
                int nl0 = (j / 3) * 16;
                int ng = c3 * 64 + nl0;
                wmma::fragment<wmma::accumulator, 16, 16, 16, float> c3f;
                wmma::fill_fragment(c3f, 0.0f);
#pragma unroll
                for (int ks = 0; ks < 4; ks++) {
                    int k = ks * 16;
                    wmma::fragment<wmma::matrix_a, 16, 16, 16, __nv_bfloat16, wmma::row_major> ahi, alo;
                    wmma::fragment<wmma::matrix_b, 16, 16, 16, __nv_bfloat16, wmma::col_major> bhi, blo;
                    wmma::load_matrix_sync(ahi, mhi + m0 * 64 + k, 64);
                    wmma::load_matrix_sync(alo, mlo + m0 * 64 + k, 64);
                    wmma::load_matrix_sync(bhi, Whi + nl0 * 64 + k, 64);
                    wmma::load_matrix_sync(blo, Wlo + nl0 * 64 + k, 64);
                    wmma::mma_sync(c3f, ahi, bhi, c3f);
                    wmma::mma_sync(c3f, ahi, blo, c3f);
                    wmma::mma_sync(c3f, alo, bhi, c3f);
                }
                wmma::store_matrix_sync(sC3 + m0 * 272 + ng, c3f, 272,
                                        wmma::mem_row_major);
            }
        }
        __syncthreads();
    }

    // dot: cw[e] = silu(C3[e] + cb1) . cW2 + cb2 (4 lanes per edge)
    if (tid < ETILE * 4) {
        int e = tid >> 2, q = tid & 3;
        float s = 0.0f;
#pragma unroll
        for (int t = 0; t < 64; t++) {
            int col = q + 4 * t;
            s += silu_f(sC3[e * 272 + col] + scb1[col]) * sdot[col];
        }
        s += __shfl_xor_sync(0xFFFFFFFFu, s, 1);
        s += __shfl_xor_sync(0xFFFFFFFFu, s, 2);
        if (q == 0 && e0 + e < N_EDGES) {
            float cw = s + cb2[l];
            int r = srow[e];
            atomicAdd(&g_cdelta[r * 3 + 0], cw * srel[e * 4 + 0]);
            atomicAdd(&g_cdelta[r * 3 + 1], cw * srel[e * 4 + 1]);
            atomicAdd(&g_cdelta[r * 3 + 2], cw * srel[e * 4 + 2]);
        }
    }
    // scatter m (fp32 in sC2) into node aggregation
    for (int idx = tid; idx < ETILE * 64; idx += TPB) {
        int e = idx >> 6, k = idx & 63;
        if (e0 + e < N_EDGES)
            atomicAdd(&g_magg[srow[e] * HID + k], sC2[e * 64 + k]);
    }
}

// ---------------- node kernel ----------------
#define NODE_SMEM_F 24576
__global__ void __launch_bounds__(256, 2) node_kernel(const float* __restrict__ nW1,
                                                      const float* __restrict__ nb1,
                                                      const float* __restrict__ nW2,
                                                      const float* __restrict__ nb2,
                                                      int l)
{
    extern __shared__ float sm[];
    float* sH = sm;
    float* sT1 = sm + 8192;
    float* Wst = sm + 16384;

    const int tid = threadIdx.x;
    const int n0 = blockIdx.x * 64;

    for (int idx = tid; idx < 64 * 64; idx += TPB) {
        int nl = idx >> 6, k = idx & 63;
        int n = n0 + nl;
        float f = 0.0f, mg = 0.0f;
        if (n < N_NODES) {
            f = g_feats[n * HID + k];
            mg = g_magg[n * HID + k];
            g_magg[n * HID + k] = 0.0f;
        }
        sH[nl * 128 + k] = f;
        sH[nl * 128 + 64 + k] = mg;
    }

    gemm_tile<128, 128, 32, 128, 128, 2, 0, true, 8, TPB>(sH, nW1 + l * 128 * 128,
                                                          nb1 + l * 128, sT1, Wst);
    gemm_tile<128, 64, 32, 128, 64, 1, 0, false, 8, TPB>(sT1, nW2 + l * 128 * 64,
                                                         nb2 + l * 64, sH, Wst);
    __syncthreads();

    for (int idx = tid; idx < 64 * 64; idx += TPB) {
        int nl = idx >> 6, k = idx & 63;
        int n = n0 + nl;
        if (n < N_NODES) g_feats[n * HID + k] += sH[idx];
    }
    if (tid < 192) {
        int n = n0 + tid / 3, d = tid % 3;
        if (n < N_NODES) {
            g_coors[n * 3 + d] += g_cdelta[n * 3 + d];
            g_cdelta[n * 3 + d] = 0.0f;
        }
    }
}

// ---------------- final projection ----------------
__global__ void __launch_bounds__(256) final_kernel(const float* __restrict__ linW,
                                                    const float* __restrict__ linb,
                                                    float* __restrict__ out)
{
    int warp = (blockIdx.x * 256 + threadIdx.x) >> 5;
    int lane = threadIdx.x & 31;
    if (warp >= N_NODES) return;
    const float* f = g_feats + warp * HID;
    float s = fmaf(f[lane], linW[lane], f[lane + 32] * linW[lane + 32]);
#pragma unroll
    for (int o = 16; o > 0; o >>= 1) s += __shfl_xor_sync(0xFFFFFFFFu, s, o);
    if (lane == 0) out[warp] = s + linb[0];
}

// ---------------- launch ----------------
extern "C" void kernel_launch(void* const* d_in, const int* in_sizes, int n_in,
                              void* d_out, int out_size)
{
    const float* x      = (const float*)d_in[0];
    const float* pos    = (const float*)d_in[1];
    const int*   ei     = (const int*)  d_in[2];
    const float* eattr  = (const float*)d_in[3];
    const float* embedW = (const float*)d_in[4];
    const float* embedb = (const float*)d_in[5];
    const float* eW1    = (const float*)d_in[6];
    const float* eb1    = (const float*)d_in[7];
    const float* eW2    = (const float*)d_in[8];
    const float* eb2    = (const float*)d_in[9];
    const float* cW1    = (const float*)d_in[10];
    const float* cb1    = (const float*)d_in[11];
    const float* cW2    = (const float*)d_in[12];
    const float* cb2    = (const float*)d_in[13];
    const float* nW1    = (const float*)d_in[14];
    const float* nb1    = (const float*)d_in[15];
    const float* nW2    = (const float*)d_in[16];
    const float* nb2    = (const float*)d_in[17];
    const float* linW   = (const float*)d_in[18];
    const float* linb   = (const float*)d_in[19];
    float* out = (float*)d_out;

    cudaFuncSetAttribute(edge_kernel, cudaFuncAttributeMaxDynamicSharedMemorySize,
                         EDGE_SMEM_F * 4);
    cudaFuncSetAttribute(prenode0_kernel, cudaFuncAttributeMaxDynamicSharedMemorySize,
                         PRE0_SMEM_F * 4);
    cudaFuncSetAttribute(prenode_kernel, cudaFuncAttributeMaxDynamicSharedMemorySize,
                         PRE_SMEM_F * 4);
    cudaFuncSetAttribute(node_kernel, cudaFuncAttributeMaxDynamicSharedMemorySize,
                         NODE_SMEM_F * 4);

    {
        int total = NL * K1 * N1 + NL * N1 + NL * K2P * 64 + NL * 64 * 256;
        pad_kernel<<<(total + 255) / 256, 256>>>(eW1, eb1, eW2, cW1);
    }

    const int egrid = (N_EDGES + ETILE - 1) / ETILE;
    const int ngrid = (N_NODES + 63) / 64;

    prenode0_kernel<<<ngrid, TPB, PRE0_SMEM_F * 4>>>(x, pos, embedW, embedb);

    for (int l = 0; l < NL; l++) {
        edge_kernel<<<egrid, TPB, EDGE_SMEM_F * 4>>>(ei, eattr, eb2, cb1, cW2,
                                                     cb2, l);
        node_kernel<<<ngrid, TPB, NODE_SMEM_F * 4>>>(nW1, nb1, nW2, nb2, l);
        if (l < NL - 1)
            prenode_kernel<<<ngrid, TPB, PRE_SMEM_F * 4>>>(l + 1);
    }
    final_kernel<<<(N_NODES * 32 + 255) / 256, 256>>>(linW, linb, out);
}

// round 12
// speedup vs baseline: 1.6270x; 1.6270x over previous
#include <cuda_runtime.h>
#include <math.h>

#define N_NODES 50000
#define N_EDGES 400000
#define HID 64
#define F_IN 8
#define NL 3

// padded dims
#define K1 132    // e_in padded (130 -> 132)
#define N1 288    // edge hidden padded (260 -> 288)
#define K2 260    // GEMM2 true K (eW2 used unpadded)
#define NPAD 50048

#define ETILE 48  // edges per block
#define TPB 256

// ---------------- device scratch (no allocations allowed) ----------------
__device__ float g_feats[N_NODES * HID];
__device__ float g_coors[N_NODES * 3];
__device__ float g_magg[N_NODES * HID];
__device__ float g_cdelta[N_NODES * 3];
__device__ float g_eW1p[NL * K1 * N1];
__device__ float g_eb1p[NL * N1];
__device__ float g_PA[NPAD * N1];   // feats @ W1a + b1 (per current layer)
__device__ float g_PB[NPAD * N1];   // feats @ W1b
__device__ float g_zbias[N1];       // stays zero (device globals zero-init)

__device__ __forceinline__ float silu_f(float v) {
    return v * __fdividef(1.0f, 1.0f + __expf(-v));
}

// packed f32x2 helpers (sm_103a FFMA2 path — only reachable via PTX)
typedef unsigned long long u64;
__device__ __forceinline__ u64 packdup(float x) {
    u64 r;
    asm("mov.b64 %0, {%1, %1};" : "=l"(r) : "r"(__float_as_uint(x)));
    return r;
}
__device__ __forceinline__ float2 unpackf2(u64 v) {
    unsigned int lo, hi;
    asm("mov.b64 {%0, %1}, %2;" : "=r"(lo), "=r"(hi) : "l"(v));
    return make_float2(__uint_as_float(lo), __uint_as_float(hi));
}
#define FFMA2(acc, a, w) \
    asm("fma.rn.f32x2 %0, %1, %2, %0;" : "+l"(acc) : "l"(a), "l"(w))

// cp.async 16B helpers (LDGSTS — register-free weight staging)
__device__ __forceinline__ void cp16(float* dst_smem, const float* src) {
    unsigned int a = (unsigned int)__cvta_generic_to_shared(dst_smem);
    asm volatile("cp.async.cg.shared.global [%0], [%1], 16;" :: "r"(a), "l"(src));
}
#define CP_COMMIT() asm volatile("cp.async.commit_group;" ::: "memory")
#define CP_WAIT0()  asm volatile("cp.async.wait_group 0;" ::: "memory")

// ---------------- GEMM tile, TPBT threads, RPT rows/thread ----------------
// C[(TPBT/32)*RPT][N] = act(A @ Wg + Bg)
// Thread (er=tid>>5, cc=tid&31): rows er*RPT..er*RPT+RPT-1.
// Cols: pair p -> (2cc+64p, 2cc+64p+1), p<P; scalar col 64P+cc if R==1.
// Wg staged via cp.async into Wst (double-buffered, KC rows/chunk, KC%4==0).
// Inner loop walks k in quads (float4 A broadcast).
// Preload sync covers A writes program-ordered before the call; no trailing
// sync (next gemm's preload sync, or an explicit one, covers the epilogue).
template<int K, int N, int KC, int AS, int CS, int P, int R, bool ACT, int RPT,
         int TPBT>
__device__ __forceinline__ void gemm_tile(const float* __restrict__ A,
                                          const float* __restrict__ Wg,
                                          const float* __restrict__ Bg,
                                          float* __restrict__ C,
                                          float* __restrict__ Wst)
{
    static_assert(KC % 4 == 0, "KC must be a multiple of 4");
    constexpr int NCHUNK = K / KC;
    constexpr int CHSZ = KC * N;
    constexpr int NLD = CHSZ / 4;     // 16B transfers per chunk
    const int tid = threadIdx.x;
    const int er = tid >> 5;
    const int cc = tid & 31;

    u64 accp[RPT][P];
    float accs[RPT];
#pragma unroll
    for (int i = 0; i < RPT; i++) {
        accs[i] = 0.0f;
#pragma unroll
        for (int p = 0; p < P; p++) accp[i][p] = 0ULL;
    }

    // preload chunk 0 into buffer 0
    for (int i = tid; i < NLD; i += TPBT) cp16(Wst + 4 * i, Wg + 4 * i);
    CP_COMMIT();
    CP_WAIT0();
    __syncthreads();

    for (int c = 0; c < NCHUNK; c++) {
        const float* buf = Wst + (c & 1) * CHSZ;
        float* nbuf = Wst + ((c + 1) & 1) * CHSZ;
        if (c + 1 < NCHUNK) {
            const float* src = Wg + (c + 1) * CHSZ;
            for (int i = tid; i < NLD; i += TPBT) cp16(nbuf + 4 * i, src + 4 * i);
            CP_COMMIT();
        }
        const int k0 = c * KC;

#pragma unroll
        for (int kk = 0; kk < KC; kk += 4) {
            u64 w[4][P];
            float ws[4];
#pragma unroll
            for (int k = 0; k < 4; k++) {
#pragma unroll
                for (int p = 0; p < P; p++)
                    w[k][p] = *(const u64*)(buf + (kk + k) * N + 2 * cc + 64 * p);
                if (R) ws[k] = buf[(kk + k) * N + 64 * P + cc];
            }
#pragma unroll
            for (int i = 0; i < RPT; i++) {
                float4 a4 = *(const float4*)(A + (er * RPT + i) * AS + k0 + kk);
                u64 a0 = packdup(a4.x);
                u64 a1 = packdup(a4.y);
                u64 a2 = packdup(a4.z);
                u64 a3 = packdup(a4.w);
#pragma unroll
                for (int p = 0; p < P; p++) {
                    FFMA2(accp[i][p], a0, w[0][p]);
                    FFMA2(accp[i][p], a1, w[1][p]);
                    FFMA2(accp[i][p], a2, w[2][p]);
                    FFMA2(accp[i][p], a3, w[3][p]);
                }
                if (R) {
                    accs[i] = fmaf(a4.x, ws[0], accs[i]);
                    accs[i] = fmaf(a4.y, ws[1], accs[i]);
                    accs[i] = fmaf(a4.z, ws[2], accs[i]);
                    accs[i] = fmaf(a4.w, ws[3], accs[i]);
                }
            }
        }
        if (c + 1 < NCHUNK) CP_WAIT0();
        __syncthreads();
    }

    // epilogue: bias + activation + store
    float2 bv[P];
    float bs = 0.0f;
#pragma unroll
    for (int p = 0; p < P; p++) bv[p] = *(const float2*)(Bg + 2 * cc + 64 * p);
    if (R) bs = Bg[64 * P + cc];
#pragma unroll
    for (int i = 0; i < RPT; i++) {
#pragma unroll
        for (int p = 0; p < P; p++) {
            float2 v = unpackf2(accp[i][p]);
            v.x += bv[p].x;
            v.y += bv[p].y;
            if (ACT) { v.x = silu_f(v.x); v.y = silu_f(v.y); }
            *(float2*)(C + (er * RPT + i) * CS + 2 * cc + 64 * p) = v;
        }
        if (R) {
            float v = accs[i] + bs;
            if (ACT) v = silu_f(v);
            C[(er * RPT + i) * CS + 64 * P + cc] = v;
        }
    }
}

// ---------------- GEMM + fused dot tile ----------------
// cw[row] = sum_col silu(A@Wg + Bg)[row][col] * sdot[col]
template<int K, int N, int KC, int AS, int P, int RPT, int TPBT>
__device__ __forceinline__ void gemm_dot_tile(const float* __restrict__ A,
                                              const float* __restrict__ Wg,
                                              const float* __restrict__ Bg,
                                              const float* __restrict__ sdot,
                                              float* __restrict__ cwout,
                                              float* __restrict__ Wst)
{
    static_assert(KC % 4 == 0, "KC must be a multiple of 4");
    constexpr int NCHUNK = K / KC;
    constexpr int CHSZ = KC * N;
    constexpr int NLD = CHSZ / 4;
    const int tid = threadIdx.x;
    const int er = tid >> 5;
    const int cc = tid & 31;

    u64 accp[RPT][P];
#pragma unroll
    for (int i = 0; i < RPT; i++)
#pragma unroll
        for (int p = 0; p < P; p++) accp[i][p] = 0ULL;

    for (int i = tid; i < NLD; i += TPBT) cp16(Wst + 4 * i, Wg + 4 * i);
    CP_COMMIT();
    CP_WAIT0();
    __syncthreads();

    for (int c = 0; c < NCHUNK; c++) {
        const float* buf = Wst + (c & 1) * CHSZ;
        float* nbuf = Wst + ((c + 1) & 1) * CHSZ;
        if (c + 1 < NCHUNK) {
            const float* src = Wg + (c + 1) * CHSZ;
            for (int i = tid; i < NLD; i += TPBT) cp16(nbuf + 4 * i, src + 4 * i);
            CP_COMMIT();
        }
        const int k0 = c * KC;
#pragma unroll
        for (int kk = 0; kk < KC; kk += 4) {
            u64 w[4][P];
#pragma unroll
            for (int k = 0; k < 4; k++)
#pragma unroll
                for (int p = 0; p < P; p++)
                    w[k][p] = *(const u64*)(buf + (kk + k) * N + 2 * cc + 64 * p);
#pragma unroll
            for (int i = 0; i < RPT; i++) {
                float4 a4 = *(const float4*)(A + (er * RPT + i) * AS + k0 + kk);
                u64 a0 = packdup(a4.x);
                u64 a1 = packdup(a4.y);
                u64 a2 = packdup(a4.z);
                u64 a3 = packdup(a4.w);
#pragma unroll
                for (int p = 0; p < P; p++) {
                    FFMA2(accp[i][p], a0, w[0][p]);
                    FFMA2(accp[i][p], a1, w[1][p]);
                    FFMA2(accp[i][p], a2, w[2][p]);
                    FFMA2(accp[i][p], a3, w[3][p]);
                }
            }
        }
        if (c + 1 < NCHUNK) CP_WAIT0();
        __syncthreads();
    }

    // epilogue: bias + silu + dot + warp reduce
    float2 bv[P], dv[P];
#pragma unroll
    for (int p = 0; p < P; p++) {
        bv[p] = *(const float2*)(Bg + 2 * cc + 64 * p);
        dv[p] = *(const float2*)(sdot + 2 * cc + 64 * p);
    }
#pragma unroll
    for (int i = 0; i < RPT; i++) {
        float s = 0.0f;
#pragma unroll
        for (int p = 0; p < P; p++) {
            float2 v = unpackf2(accp[i][p]);
            s += silu_f(v.x + bv[p].x) * dv[p].x;
            s += silu_f(v.y + bv[p].y) * dv[p].y;
        }
#pragma unroll
        for (int o = 16; o > 0; o >>= 1) s += __shfl_xor_sync(0xFFFFFFFFu, s, o);
        if (cc == 0) cwout[er * RPT + i] = s;
    }
}

// ---------------- weight padding / prep (eW1 only) ----------------
__global__ void __launch_bounds__(256) pad_kernel(const float* __restrict__ eW1,
                                                  const float* __restrict__ eb1)
{
    const int A = NL * K1 * N1;
    const int B = NL * N1;
    int i = blockIdx.x * 256 + threadIdx.x;
    if (i < A) {
        int l = i / (K1 * N1);
        int r = (i / N1) % K1;
        int j = i % N1;
        g_eW1p[i] = (r < 130 && j < 260) ? eW1[(l * 130 + r) * 260 + j] : 0.0f;
    } else if (i < A + B) {
        int ii = i - A;
        int l = ii / N1, j = ii % N1;
        g_eb1p[ii] = (j < 260) ? eb1[l * 260 + j] : 0.0f;
    }
}

// ---------------- embed + pos copy ----------------
__global__ void __launch_bounds__(256) embed_kernel(const float* __restrict__ x,
                                                    const float* __restrict__ pos,
                                                    const float* __restrict__ W,
                                                    const float* __restrict__ b)
{
    int idx = blockIdx.x * 256 + threadIdx.x;
    if (idx < N_NODES * 3) g_coors[idx] = pos[idx];
    if (idx < N_NODES * HID) {
        int n = idx >> 6, j = idx & 63;
        float acc = b[j];
#pragma unroll
        for (int k = 0; k < F_IN; k++) acc = fmaf(x[n * F_IN + k], W[k * HID + j], acc);
        g_feats[idx] = acc;
    }
}

// ---------------- per-node precompute (+ zero of agg buffers) ----------------
// PA = feats@W1a + b1, PB = feats@W1b; also zeroes magg/cdelta for this slice.
// smem: sF [0,4096), Wst [4096,13312)  (2 x 4608)
#define PRE_SMEM_F 13312

__global__ void __launch_bounds__(256, 2) prenode_kernel(int l)
{
    extern __shared__ float sm[];
    float* sF = sm;
    float* Wst = sm + 4096;

    const int tid = threadIdx.x;
    const int n0 = blockIdx.x * 64;

    for (int idx = tid; idx < 64 * 64; idx += TPB) {
        int nl = idx >> 6, k = idx & 63;
        int n = n0 + nl;
        float f = 0.0f;
        if (n < N_NODES) {
            f = g_feats[n * HID + k];
            g_magg[n * HID + k] = 0.0f;   // fused zeroing (pre-edge, same stream)
        }
        sF[idx] = f;
    }
    if (tid < 192) {
        int n = n0 + tid / 3;
        int d = tid % 3;
        if (n < N_NODES) g_cdelta[n * 3 + d] = 0.0f;
    }

    const float* W1 = g_eW1p + l * K1 * N1;
    gemm_tile<64, N1, 16, 64, N1, 4, 1, false, 8, TPB>(sF, W1, g_eb1p + l * N1,
                                                       g_PA + n0 * N1, Wst);
    gemm_tile<64, N1, 16, 64, N1, 4, 1, false, 8, TPB>(sF, W1 + 64 * N1, g_zbias,
                                                       g_PB + n0 * N1, Wst);
}

// ---------------- edge kernel (48 edges/block, 256 threads, 2 CTA/SM) -----
// smem float layout:
//   R1    [0, 13824)      : h1 (48x288)
//   mT    [13824, 16896)  : m (48x64)
//   Wst   [16896, 25088)  : double-buffered weight staging (2 x 4096)
//   sWea  [25088, 25376)  : eW1 row 128 (288)
//   sWdist[25376, 25664)  : eW1 row 129 (288)
//   scw   [25664, 25712)  : fused dot output (48)
//   srow  [25712, 25760)  : int
//   scol  [25760, 25808)  : int
//   srel  [25808, 26000)  : rx,ry,rz,dist per edge
//   sea   [26000, 26048)  : edge_attr
//   sdot  [26048, 26304)  : cW2 (256)
#define EDGE_SMEM_F 26304

__global__ void __launch_bounds__(256, 2) edge_kernel(const int* __restrict__ ei,
                                                      const float* __restrict__ eattr,
                                                      const float* __restrict__ eW2,
                                                      const float* __restrict__ eb2,
                                                      const float* __restrict__ cW1,
                                                      const float* __restrict__ cb1,
                                                      const float* __restrict__ cW2,
                                                      const float* __restrict__ cb2,
                                                      int l)
{
    extern __shared__ float sm[];
    float* R1 = sm;
    float* mT = sm + 13824;
    float* Wst = sm + 16896;
    float* sWea = sm + 25088;
    float* sWdist = sm + 25376;
    float* scw = sm + 25664;
    int* srow = (int*)(sm + 25712);
    int* scol = (int*)(sm + 25760);
    float* srel = sm + 25808;
    float* sea = sm + 26000;
    float* sdot = sm + 26048;

    const int tid = threadIdx.x;
    const int e0 = blockIdx.x * ETILE;

    // phase 0a: scalars + small weight vectors
    sdot[tid] = cW2[l * 256 + tid];
    {
        const float* Wea = g_eW1p + l * K1 * N1 + 128 * N1;
        for (int idx = tid; idx < 2 * N1; idx += TPB) {
            if (idx < N1) sWea[idx] = Wea[idx];
            else sWdist[idx - N1] = Wea[N1 + (idx - N1)];
        }
    }
    if (tid < ETILE) {
        int e = e0 + tid;
        int r = 0, c = 0;
        float ea = 0.0f;
        if (e < N_EDGES) {
            r = ei[e];
            c = ei[N_EDGES + e];
            ea = eattr[e];
        }
        srow[tid] = r;
        scol[tid] = c;
        float rx = g_coors[r * 3 + 0] - g_coors[c * 3 + 0];
        float ry = g_coors[r * 3 + 1] - g_coors[c * 3 + 1];
        float rz = g_coors[r * 3 + 2] - g_coors[c * 3 + 2];
        srel[tid * 4 + 0] = rx;
        srel[tid * 4 + 1] = ry;
        srel[tid * 4 + 2] = rz;
        srel[tid * 4 + 3] = rx * rx + ry * ry + rz * rz;
        sea[tid] = ea;
    }
    __syncthreads();

    // phase A: h1[e][:] = silu(PA[row] + PB[col] + ea*Wea + dist*Wdist)
    for (int idx = tid; idx < ETILE * 72; idx += TPB) {
        int e = idx / 72, q = idx - e * 72;
        float4 a = ((const float4*)(g_PA + srow[e] * N1))[q];
        float4 b = ((const float4*)(g_PB + scol[e] * N1))[q];
        float4 we = ((const float4*)sWea)[q];
        float4 wd = ((const float4*)sWdist)[q];
        float ea = sea[e], di = srel[e * 4 + 3];
        float4 v;
        v.x = silu_f(fmaf(di, wd.x, fmaf(ea, we.x, a.x + b.x)));
        v.y = silu_f(fmaf(di, wd.y, fmaf(ea, we.y, a.y + b.y)));
        v.z = silu_f(fmaf(di, wd.z, fmaf(ea, we.z, a.z + b.z)));
        v.w = silu_f(fmaf(di, wd.w, fmaf(ea, we.w, a.w + b.w)));
        ((float4*)(R1 + e * N1))[q] = v;
    }

    // GEMM2: m = silu(h1[:, :260] @ eW2 + eb2)   (preload sync covers phase A)
    gemm_tile<K2, 64, 52, N1, 64, 1, 0, true, 6, TPB>(R1, eW2 + l * K2 * HID,
                                                      eb2 + l * HID, mT, Wst);
    // GEMM3 + dot fused: scw[e] = silu(m @ cW1 + cb1) . cW2
    gemm_dot_tile<64, 256, 16, 64, 4, 6, TPB>(mT, cW1 + l * 64 * 256,
                                              cb1 + l * 256, sdot, scw, Wst);
    __syncthreads();

    // coords atomics
    if (tid < ETILE) {
        int e = tid;
        if (e0 + e < N_EDGES) {
            float cw = scw[e] + cb2[l];
            int r = srow[e];
            atomicAdd(&g_cdelta[r * 3 + 0], cw * srel[e * 4 + 0]);
            atomicAdd(&g_cdelta[r * 3 + 1], cw * srel[e * 4 + 1]);
            atomicAdd(&g_cdelta[r * 3 + 2], cw * srel[e * 4 + 2]);
        }
    }
    // scatter m into node aggregation
    for (int idx = tid; idx < ETILE * 64; idx += TPB) {
        int e = idx >> 6, k = idx & 63;
        if (e0 + e < N_EDGES)
            atomicAdd(&g_magg[srow[e] * HID + k], mT[e * 64 + k]);
    }
}

// ---------------- node kernel (64 nodes/block, 256 threads) ----------------
// smem: sH [0,8192), sT1 [8192,16384), Wst [16384,24576)  (2 x 4096)
#define NODE_SMEM_F 24576

__global__ void __launch_bounds__(256, 2) node_kernel(const float* __restrict__ nW1,
                                                      const float* __restrict__ nb1,
                                                      const float* __restrict__ nW2,
                                                      const float* __restrict__ nb2,
                                                      int l)
{
    extern __shared__ float sm[];
    float* sH = sm;
    float* sT1 = sm + 8192;
    float* Wst = sm + 16384;

    const int tid = threadIdx.x;
    const int n0 = blockIdx.x * 64;

    for (int idx = tid; idx < 64 * 64; idx += TPB) {
        int nl = idx >> 6, k = idx & 63;
        int n = n0 + nl;
        float f = 0.0f, mg = 0.0f;
        if (n < N_NODES) { f = g_feats[n * HID + k]; mg = g_magg[n * HID + k]; }
        sH[nl * 128 + k] = f;
        sH[nl * 128 + 64 + k] = mg;
    }

    gemm_tile<128, 128, 32, 128, 128, 2, 0, true, 8, TPB>(sH, nW1 + l * 128 * 128,
                                                          nb1 + l * 128, sT1, Wst);
    gemm_tile<128, 64, 32, 128, 64, 1, 0, false, 8, TPB>(sT1, nW2 + l * 128 * 64,
                                                         nb2 + l * 64, sH, Wst);
    __syncthreads();

    for (int idx = tid; idx < 64 * 64; idx += TPB) {
        int nl = idx >> 6, k = idx & 63;
        int n = n0 + nl;
        if (n < N_NODES) g_feats[n * HID + k] += sH[idx];
    }
    if (tid < 192) {
        int n = n0 + tid / 3;
        int d = tid % 3;
        if (n < N_NODES) g_coors[n * 3 + d] += g_cdelta[n * 3 + d];
    }
}

// ---------------- final projection ----------------
__global__ void __launch_bounds__(256) final_kernel(const float* __restrict__ linW,
                                                    const float* __restrict__ linb,
                                                    float* __restrict__ out)
{
    int warp = (blockIdx.x * 256 + threadIdx.x) >> 5;
    int lane = threadIdx.x & 31;
    if (warp >= N_NODES) return;
    const float* f = g_feats + warp * HID;
    float s = fmaf(f[lane], linW[lane], f[lane + 32] * linW[lane + 32]);
#pragma unroll
    for (int o = 16; o > 0; o >>= 1) s += __shfl_xor_sync(0xFFFFFFFFu, s, o);
    if (lane == 0) out[warp] = s + linb[0];
}

// ---------------- launch ----------------
extern "C" void kernel_launch(void* const* d_in, const int* in_sizes, int n_in,
                              void* d_out, int out_size)
{
    const float* x      = (const float*)d_in[0];
    const float* pos    = (const float*)d_in[1];
    const int*   ei     = (const int*)  d_in[2];
    const float* eattr  = (const float*)d_in[3];
    const float* embedW = (const float*)d_in[4];
    const float* embedb = (const float*)d_in[5];
    const float* eW1    = (const float*)d_in[6];
    const float* eb1    = (const float*)d_in[7];
    const float* eW2    = (const float*)d_in[8];
    const float* eb2    = (const float*)d_in[9];
    const float* cW1    = (const float*)d_in[10];
    const float* cb1    = (const float*)d_in[11];
    const float* cW2    = (const float*)d_in[12];
    const float* cb2    = (const float*)d_in[13];
    const float* nW1    = (const float*)d_in[14];
    const float* nb1    = (const float*)d_in[15];
    const float* nW2    = (const float*)d_in[16];
    const float* nb2    = (const float*)d_in[17];
    const float* linW   = (const float*)d_in[18];
    const float* linb   = (const float*)d_in[19];
    float* out = (float*)d_out;

    cudaFuncSetAttribute(edge_kernel, cudaFuncAttributeMaxDynamicSharedMemorySize,
                         EDGE_SMEM_F * 4);
    cudaFuncSetAttribute(node_kernel, cudaFuncAttributeMaxDynamicSharedMemorySize,
                         NODE_SMEM_F * 4);
    cudaFuncSetAttribute(prenode_kernel, cudaFuncAttributeMaxDynamicSharedMemorySize,
                         PRE_SMEM_F * 4);

    {
        int total = NL * K1 * N1 + NL * N1;
        pad_kernel<<<(total + 255) / 256, 256>>>(eW1, eb1);
    }
    embed_kernel<<<(N_NODES * HID + 255) / 256, 256>>>(x, pos, embedW, embedb);

    const int egrid = (N_EDGES + ETILE - 1) / ETILE;
    const int ngrid = (N_NODES + 63) / 64;
    for (int l = 0; l < NL; l++) {
        prenode_kernel<<<ngrid, TPB, PRE_SMEM_F * 4>>>(l);
        edge_kernel<<<egrid, TPB, EDGE_SMEM_F * 4>>>(ei, eattr, eW2, eb2, cW1, cb1,
                                                     cW2, cb2, l);
        node_kernel<<<ngrid, TPB, NODE_SMEM_F * 4>>>(nW1, nb1, nW2, nb2, l);
    }
    final_kernel<<<(N_NODES * 32 + 255) / 256, 256>>>(linW, linb, out);
}

// round 13
// speedup vs baseline: 1.6793x; 1.0321x over previous
#include <cuda_runtime.h>
#include <math.h>

#define N_NODES 50000
#define N_EDGES 400000
#define HID 64
#define F_IN 8
#define NL 3

// padded dims
#define K1 132    // e_in padded (130 -> 132)
#define N1 288    // edge hidden padded (260 -> 288)
#define K2 260    // GEMM2 true K (eW2 used unpadded)
#define NPAD 50048

#define ETILE 48  // edges per block
#define TPB 256

// ---------------- device scratch (no allocations allowed) ----------------
__device__ float g_feats[N_NODES * HID];
__device__ float g_coors[N_NODES * 3];
__device__ float g_magg[N_NODES * HID];
__device__ float g_cdelta[N_NODES * 3];
__device__ float g_eW1p[NL * K1 * N1];
__device__ float g_eb1p[NL * N1];
__device__ float g_PA[NPAD * N1];   // feats @ W1a + b1 (per current layer)
__device__ float g_PB[NPAD * N1];   // feats @ W1b
__device__ float g_zbias[N1];       // stays zero (device globals zero-init)

__device__ __forceinline__ float silu_f(float v) {
    return v * __fdividef(1.0f, 1.0f + __expf(-v));
}

// packed f32x2 helpers (sm_103a FFMA2 path — only reachable via PTX)
typedef unsigned long long u64;
__device__ __forceinline__ u64 packdup(float x) {
    u64 r;
    asm("mov.b64 %0, {%1, %1};" : "=l"(r) : "r"(__float_as_uint(x)));
    return r;
}
__device__ __forceinline__ float2 unpackf2(u64 v) {
    unsigned int lo, hi;
    asm("mov.b64 {%0, %1}, %2;" : "=r"(lo), "=r"(hi) : "l"(v));
    return make_float2(__uint_as_float(lo), __uint_as_float(hi));
}
#define FFMA2(acc, a, w) \
    asm("fma.rn.f32x2 %0, %1, %2, %0;" : "+l"(acc) : "l"(a), "l"(w))

// cp.async 16B helpers (LDGSTS — register-free weight staging)
__device__ __forceinline__ void cp16(float* dst_smem, const float* src) {
    unsigned int a = (unsigned int)__cvta_generic_to_shared(dst_smem);
    asm volatile("cp.async.cg.shared.global [%0], [%1], 16;" :: "r"(a), "l"(src));
}
#define CP_COMMIT() asm volatile("cp.async.commit_group;" ::: "memory")
#define CP_WAIT0()  asm volatile("cp.async.wait_group 0;" ::: "memory")

// ---------------- GEMM tile, TPBT threads, RPT rows/thread ----------------
// C[(TPBT/32)*RPT][N] = act(A @ Wg + Bg)
// Thread (er=tid>>5, cc=tid&31): rows er*RPT..er*RPT+RPT-1.
// Cols: pair p -> (2cc+64p, 2cc+64p+1), p<P; scalar col 64P+cc if R==1.
// Wg staged via cp.async into Wst (double-buffered, KC rows/chunk, KC%4==0).
// Inner loop: A read float4-per-quad into a4[RPT] registers; W register
// double-buffered one k ahead (wc/wn) so the LDS latency overlaps the FMAs
// of the previous k instead of serializing with them.
template<int K, int N, int KC, int AS, int CS, int P, int R, bool ACT, int RPT,
         int TPBT>
__device__ __forceinline__ void gemm_tile(const float* __restrict__ A,
                                          const float* __restrict__ Wg,
                                          const float* __restrict__ Bg,
                                          float* __restrict__ C,
                                          float* __restrict__ Wst)
{
    static_assert(KC % 4 == 0, "KC must be a multiple of 4");
    constexpr int NCHUNK = K / KC;
    constexpr int CHSZ = KC * N;
    constexpr int NLD = CHSZ / 4;     // 16B transfers per chunk
    const int tid = threadIdx.x;
    const int er = tid >> 5;
    const int cc = tid & 31;

    u64 accp[RPT][P];
    float accs[RPT];
#pragma unroll
    for (int i = 0; i < RPT; i++) {
        accs[i] = 0.0f;
#pragma unroll
        for (int p = 0; p < P; p++) accp[i][p] = 0ULL;
    }

    // preload chunk 0 into buffer 0
    for (int i = tid; i < NLD; i += TPBT) cp16(Wst + 4 * i, Wg + 4 * i);
    CP_COMMIT();
    CP_WAIT0();
    __syncthreads();

    for (int c = 0; c < NCHUNK; c++) {
        const float* buf = Wst + (c & 1) * CHSZ;
        float* nbuf = Wst + ((c + 1) & 1) * CHSZ;
        if (c + 1 < NCHUNK) {
            const float* src = Wg + (c + 1) * CHSZ;
            for (int i = tid; i < NLD; i += TPBT) cp16(nbuf + 4 * i, src + 4 * i);
            CP_COMMIT();
        }
        const int k0 = c * KC;

        // W register double-buffer, primed with local k=0
        u64 wc[P], wn[P];
        float wsc = 0.0f, wsn = 0.0f;
#pragma unroll
        for (int p = 0; p < P; p++) wc[p] = *(const u64*)(buf + 2 * cc + 64 * p);
        if (R) wsc = buf[64 * P + cc];

#pragma unroll
        for (int kk = 0; kk < KC; kk += 4) {
            // A quad per row (held across the 4 inner k's)
            float4 a4[RPT];
#pragma unroll
            for (int i = 0; i < RPT; i++)
                a4[i] = *(const float4*)(A + (er * RPT + i) * AS + k0 + kk);
#pragma unroll
            for (int k = 0; k < 4; k++) {
                const int kn = kk + k + 1;
                if (kn < KC) {
#pragma unroll
                    for (int p = 0; p < P; p++)
                        wn[p] = *(const u64*)(buf + kn * N + 2 * cc + 64 * p);
                    if (R) wsn = buf[kn * N + 64 * P + cc];
                }
#pragma unroll
                for (int i = 0; i < RPT; i++) {
                    float av = (k == 0) ? a4[i].x : (k == 1) ? a4[i].y
                             : (k == 2) ? a4[i].z : a4[i].w;
                    u64 ad = packdup(av);
#pragma unroll
                    for (int p = 0; p < P; p++) FFMA2(accp[i][p], ad, wc[p]);
                    if (R) accs[i] = fmaf(av, wsc, accs[i]);
                }
#pragma unroll
                for (int p = 0; p < P; p++) wc[p] = wn[p];
                if (R) wsc = wsn;
            }
        }
        if (c + 1 < NCHUNK) CP_WAIT0();
        __syncthreads();
    }

    // epilogue: bias + activation + store
    float2 bv[P];
    float bs = 0.0f;
#pragma unroll
    for (int p = 0; p < P; p++) bv[p] = *(const float2*)(Bg + 2 * cc + 64 * p);
    if (R) bs = Bg[64 * P + cc];
#pragma unroll
    for (int i = 0; i < RPT; i++) {
#pragma unroll
        for (int p = 0; p < P; p++) {
            float2 v = unpackf2(accp[i][p]);
            v.x += bv[p].x;
            v.y += bv[p].y;
            if (ACT) { v.x = silu_f(v.x); v.y = silu_f(v.y); }
            *(float2*)(C + (er * RPT + i) * CS + 2 * cc + 64 * p) = v;
        }
        if (R) {
            float v = accs[i] + bs;
            if (ACT) v = silu_f(v);
            C[(er * RPT + i) * CS + 64 * P + cc] = v;
        }
    }
}

// ---------------- GEMM + fused dot tile ----------------
// cw[row] = sum_col silu(A@Wg + Bg)[row][col] * sdot[col]
// Same k-pipelined W double-buffer as gemm_tile.
template<int K, int N, int KC, int AS, int P, int RPT, int TPBT>
__device__ __forceinline__ void gemm_dot_tile(const float* __restrict__ A,
                                              const float* __restrict__ Wg,
                                              const float* __restrict__ Bg,
                                              const float* __restrict__ sdot,
                                              float* __restrict__ cwout,
                                              float* __restrict__ Wst)
{
    static_assert(KC % 4 == 0, "KC must be a multiple of 4");
    constexpr int NCHUNK = K / KC;
    constexpr int CHSZ = KC * N;
    constexpr int NLD = CHSZ / 4;
    const int tid = threadIdx.x;
    const int er = tid >> 5;
    const int cc = tid & 31;

    u64 accp[RPT][P];
#pragma unroll
    for (int i = 0; i < RPT; i++)
#pragma unroll
        for (int p = 0; p < P; p++) accp[i][p] = 0ULL;

    for (int i = tid; i < NLD; i += TPBT) cp16(Wst + 4 * i, Wg + 4 * i);
    CP_COMMIT();
    CP_WAIT0();
    __syncthreads();

    for (int c = 0; c < NCHUNK; c++) {
        const float* buf = Wst + (c & 1) * CHSZ;
        float* nbuf = Wst + ((c + 1) & 1) * CHSZ;
        if (c + 1 < NCHUNK) {
            const float* src = Wg + (c + 1) * CHSZ;
            for (int i = tid; i < NLD; i += TPBT) cp16(nbuf + 4 * i, src + 4 * i);
            CP_COMMIT();
        }
        const int k0 = c * KC;

        u64 wc[P], wn[P];
#pragma unroll
        for (int p = 0; p < P; p++) wc[p] = *(const u64*)(buf + 2 * cc + 64 * p);

#pragma unroll
        for (int kk = 0; kk < KC; kk += 4) {
            float4 a4[RPT];
#pragma unroll
            for (int i = 0; i < RPT; i++)
                a4[i] = *(const float4*)(A + (er * RPT + i) * AS + k0 + kk);
#pragma unroll
            for (int k = 0; k < 4; k++) {
                const int kn = kk + k + 1;
                if (kn < KC) {
#pragma unroll
                    for (int p = 0; p < P; p++)
                        wn[p] = *(const u64*)(buf + kn * N + 2 * cc + 64 * p);
                }
#pragma unroll
                for (int i = 0; i < RPT; i++) {
                    float av = (k == 0) ? a4[i].x : (k == 1) ? a4[i].y
                             : (k == 2) ? a4[i].z : a4[i].w;
                    u64 ad = packdup(av);
#pragma unroll
                    for (int p = 0; p < P; p++) FFMA2(accp[i][p], ad, wc[p]);
                }
#pragma unroll
                for (int p = 0; p < P; p++) wc[p] = wn[p];
            }
        }
        if (c + 1 < NCHUNK) CP_WAIT0();
        __syncthreads();
    }

    // epilogue: bias + silu + dot + warp reduce
    float2 bv[P], dv[P];
#pragma unroll
    for (int p = 0; p < P; p++) {
        bv[p] = *(const float2*)(Bg + 2 * cc + 64 * p);
        dv[p] = *(const float2*)(sdot + 2 * cc + 64 * p);
    }
#pragma unroll
    for (int i = 0; i < RPT; i++) {
        float s = 0.0f;
#pragma unroll
        for (int p = 0; p < P; p++) {
            float2 v = unpackf2(accp[i][p]);
            s += silu_f(v.x + bv[p].x) * dv[p].x;
            s += silu_f(v.y + bv[p].y) * dv[p].y;
        }
#pragma unroll
        for (int o = 16; o > 0; o >>= 1) s += __shfl_xor_sync(0xFFFFFFFFu, s, o);
        if (cc == 0) cwout[er * RPT + i] = s;
    }
}

// ---------------- weight padding / prep (eW1 only) ----------------
__global__ void __launch_bounds__(256) pad_kernel(const float* __restrict__ eW1,
                                                  const float* __restrict__ eb1)
{
    const int A = NL * K1 * N1;
    const int B = NL * N1;
    int i = blockIdx.x * 256 + threadIdx.x;
    if (i < A) {
        int l = i / (K1 * N1);
        int r = (i / N1) % K1;
        int j = i % N1;
        g_eW1p[i] = (r < 130 && j < 260) ? eW1[(l * 130 + r) * 260 + j] : 0.0f;
    } else if (i < A + B) {
        int ii = i - A;
        int l = ii / N1, j = ii % N1;
        g_eb1p[ii] = (j < 260) ? eb1[l * 260 + j] : 0.0f;
    }
}

// ---------------- embed + pos copy ----------------
__global__ void __launch_bounds__(256) embed_kernel(const float* __restrict__ x,
                                                    const float* __restrict__ pos,
                                                    const float* __restrict__ W,
                                                    const float* __restrict__ b)
{
    int idx = blockIdx.x * 256 + threadIdx.x;
    if (idx < N_NODES * 3) g_coors[idx] = pos[idx];
    if (idx < N_NODES * HID) {
        int n = idx >> 6, j = idx & 63;
        float acc = b[j];
#pragma unroll
        for (int k = 0; k < F_IN; k++) acc = fmaf(x[n * F_IN + k], W[k * HID + j], acc);
        g_feats[idx] = acc;
    }
}

// ---------------- per-node precompute (+ zero of agg buffers) ----------------
// PA = feats@W1a + b1, PB = feats@W1b; also zeroes magg/cdelta for this slice.
// smem: sF [0,4096), Wst [4096,13312)  (2 x 4608)
#define PRE_SMEM_F 13312

__global__ void __launch_bounds__(256, 2) prenode_kernel(int l)
{
    extern __shared__ float sm[];
    float* sF = sm;
    float* Wst = sm + 4096;

    const int tid = threadIdx.x;
    const int n0 = blockIdx.x * 64;

    for (int idx = tid; idx < 64 * 64; idx += TPB) {
        int nl = idx >> 6, k = idx & 63;
        int n = n0 + nl;
        float f = 0.0f;
        if (n < N_NODES) {
            f = g_feats[n * HID + k];
            g_magg[n * HID + k] = 0.0f;   // fused zeroing (pre-edge, same stream)
        }
        sF[idx] = f;
    }
    if (tid < 192) {
        int n = n0 + tid / 3;
        int d = tid % 3;
        if (n < N_NODES) g_cdelta[n * 3 + d] = 0.0f;
    }

    const float* W1 = g_eW1p + l * K1 * N1;
    gemm_tile<64, N1, 16, 64, N1, 4, 1, false, 8, TPB>(sF, W1, g_eb1p + l * N1,
                                                       g_PA + n0 * N1, Wst);
    gemm_tile<64, N1, 16, 64, N1, 4, 1, false, 8, TPB>(sF, W1 + 64 * N1, g_zbias,
                                                       g_PB + n0 * N1, Wst);
}

// ---------------- edge kernel (48 edges/block, 256 threads, 2 CTA/SM) -----
// smem float layout:
//   R1    [0, 13824)      : h1 (48x288, cols 260..287 unused)
//   mT    [13824, 16896)  : m (48x64)
//   Wst   [16896, 25088)  : double-buffered weight staging (2 x 4096)
//   sWea  [25088, 25376)  : eW1 row 128 (288)
//   sWdist[25376, 25664)  : eW1 row 129 (288)
//   scw   [25664, 25712)  : fused dot output (48)
//   srow  [25712, 25760)  : int
//   scol  [25760, 25808)  : int
//   srel  [25808, 26000)  : rx,ry,rz,dist per edge
//   sea   [26000, 26048)  : edge_attr
//   sdot  [26048, 26304)  : cW2 (256)
#define EDGE_SMEM_F 26304

__global__ void __launch_bounds__(256, 2) edge_kernel(const int* __restrict__ ei,
                                                      const float* __restrict__ eattr,
                                                      const float* __restrict__ eW2,
                                                      const float* __restrict__ eb2,
                                                      const float* __restrict__ cW1,
                                                      const float* __restrict__ cb1,
                                                      const float* __restrict__ cW2,
                                                      const float* __restrict__ cb2,
                                                      int l)
{
    extern __shared__ float sm[];
    float* R1 = sm;
    float* mT = sm + 13824;
    float* Wst = sm + 16896;
    float* sWea = sm + 25088;
    float* sWdist = sm + 25376;
    float* scw = sm + 25664;
    int* srow = (int*)(sm + 25712);
    int* scol = (int*)(sm + 25760);
    float* srel = sm + 25808;
    float* sea = sm + 26000;
    float* sdot = sm + 26048;

    const int tid = threadIdx.x;
    const int e0 = blockIdx.x * ETILE;

    // phase 0a: scalars + small weight vectors
    sdot[tid] = cW2[l * 256 + tid];
    {
        const float* Wea = g_eW1p + l * K1 * N1 + 128 * N1;
        for (int idx = tid; idx < 2 * N1; idx += TPB) {
            if (idx < N1) sWea[idx] = Wea[idx];
            else sWdist[idx - N1] = Wea[N1 + (idx - N1)];
        }
    }
    if (tid < ETILE) {
        int e = e0 + tid;
        int r = 0, c = 0;
        float ea = 0.0f;
        if (e < N_EDGES) {
            r = ei[e];
            c = ei[N_EDGES + e];
            ea = eattr[e];
        }
        srow[tid] = r;
        scol[tid] = c;
        float rx = g_coors[r * 3 + 0] - g_coors[c * 3 + 0];
        float ry = g_coors[r * 3 + 1] - g_coors[c * 3 + 1];
        float rz = g_coors[r * 3 + 2] - g_coors[c * 3 + 2];
        srel[tid * 4 + 0] = rx;
        srel[tid * 4 + 1] = ry;
        srel[tid * 4 + 2] = rz;
        srel[tid * 4 + 3] = rx * rx + ry * ry + rz * rz;
        sea[tid] = ea;
    }
    __syncthreads();

    // phase A: h1[e][0:260] = silu(PA[row] + PB[col] + ea*Wea + dist*Wdist)
    // (cols 260..287 never read by GEMM2 since K2=260)
    for (int idx = tid; idx < ETILE * 65; idx += TPB) {
        int e = idx / 65, q = idx - e * 65;
        float4 a = ((const float4*)(g_PA + srow[e] * N1))[q];
        float4 b = ((const float4*)(g_PB + scol[e] * N1))[q];
        float4 we = ((const float4*)sWea)[q];
        float4 wd = ((const float4*)sWdist)[q];
        float ea = sea[e], di = srel[e * 4 + 3];
        float4 v;
        v.x = silu_f(fmaf(di, wd.x, fmaf(ea, we.x, a.x + b.x)));
        v.y = silu_f(fmaf(di, wd.y, fmaf(ea, we.y, a.y + b.y)));
        v.z = silu_f(fmaf(di, wd.z, fmaf(ea, we.z, a.z + b.z)));
        v.w = silu_f(fmaf(di, wd.w, fmaf(ea, we.w, a.w + b.w)));
        ((float4*)(R1 + e * N1))[q] = v;
    }

    // GEMM2: m = silu(h1[:, :260] @ eW2 + eb2)   (preload sync covers phase A)
    gemm_tile<K2, 64, 52, N1, 64, 1, 0, true, 6, TPB>(R1, eW2 + l * K2 * HID,
                                                      eb2 + l * HID, mT, Wst);
    // GEMM3 + dot fused: scw[e] = silu(m @ cW1 + cb1) . cW2
    gemm_dot_tile<64, 256, 16, 64, 4, 6, TPB>(mT, cW1 + l * 64 * 256,
                                              cb1 + l * 256, sdot, scw, Wst);
    __syncthreads();

    // coords atomics
    if (tid < ETILE) {
        int e = tid;
        if (e0 + e < N_EDGES) {
            float cw = scw[e] + cb2[l];
            int r = srow[e];
            atomicAdd(&g_cdelta[r * 3 + 0], cw * srel[e * 4 + 0]);
            atomicAdd(&g_cdelta[r * 3 + 1], cw * srel[e * 4 + 1]);
            atomicAdd(&g_cdelta[r * 3 + 2], cw * srel[e * 4 + 2]);
        }
    }
    // scatter m into node aggregation
    for (int idx = tid; idx < ETILE * 64; idx += TPB) {
        int e = idx >> 6, k = idx & 63;
        if (e0 + e < N_EDGES)
            atomicAdd(&g_magg[srow[e] * HID + k], mT[e * 64 + k]);
    }
}

// ---------------- node kernel (64 nodes/block, 256 threads) ----------------
// smem: sH [0,8192), sT1 [8192,16384), Wst [16384,24576)  (2 x 4096)
#define NODE_SMEM_F 24576

__global__ void __launch_bounds__(256, 2) node_kernel(const float* __restrict__ nW1,
                                                      const float* __restrict__ nb1,
                                                      const float* __restrict__ nW2,
                                                      const float* __restrict__ nb2,
                                                      int l)
{
    extern __shared__ float sm[];
    float* sH = sm;
    float* sT1 = sm + 8192;
    float* Wst = sm + 16384;

    const int tid = threadIdx.x;
    const int n0 = blockIdx.x * 64;

    for (int idx = tid; idx < 64 * 64; idx += TPB) {
        int nl = idx >> 6, k = idx & 63;
        int n = n0 + nl;
        float f = 0.0f, mg = 0.0f;
        if (n < N_NODES) { f = g_feats[n * HID + k]; mg = g_magg[n * HID + k]; }
        sH[nl * 128 + k] = f;
        sH[nl * 128 + 64 + k] = mg;
    }

    gemm_tile<128, 128, 32, 128, 128, 2, 0, true, 8, TPB>(sH, nW1 + l * 128 * 128,
                                                          nb1 + l * 128, sT1, Wst);
    gemm_tile<128, 64, 32, 128, 64, 1, 0, false, 8, TPB>(sT1, nW2 + l * 128 * 64,
                                                         nb2 + l * 64, sH, Wst);
    __syncthreads();

    for (int idx = tid; idx < 64 * 64; idx += TPB) {
        int nl = idx >> 6, k = idx & 63;
        int n = n0 + nl;
        if (n < N_NODES) g_feats[n * HID + k] += sH[idx];
    }
    if (tid < 192) {
        int n = n0 + tid / 3;
        int d = tid % 3;
        if (n < N_NODES) g_coors[n * 3 + d] += g_cdelta[n * 3 + d];
    }
}

// ---------------- final projection ----------------
__global__ void __launch_bounds__(256) final_kernel(const float* __restrict__ linW,
                                                    const float* __restrict__ linb,
                                                    float* __restrict__ out)
{
    int warp = (blockIdx.x * 256 + threadIdx.x) >> 5;
    int lane = threadIdx.x & 31;
    if (warp >= N_NODES) return;
    const float* f = g_feats + warp * HID;
    float s = fmaf(f[lane], linW[lane], f[lane + 32] * linW[lane + 32]);
#pragma unroll
    for (int o = 16; o > 0; o >>= 1) s += __shfl_xor_sync(0xFFFFFFFFu, s, o);
    if (lane == 0) out[warp] = s + linb[0];
}

// ---------------- launch ----------------
extern "C" void kernel_launch(void* const* d_in, const int* in_sizes, int n_in,
                              void* d_out, int out_size)
{
    const float* x      = (const float*)d_in[0];
    const float* pos    = (const float*)d_in[1];
    const int*   ei     = (const int*)  d_in[2];
    const float* eattr  = (const float*)d_in[3];
    const float* embedW = (const float*)d_in[4];
    const float* embedb = (const float*)d_in[5];
    const float* eW1    = (const float*)d_in[6];
    const float* eb1    = (const float*)d_in[7];
    const float* eW2    = (const float*)d_in[8];
    const float* eb2    = (const float*)d_in[9];
    const float* cW1    = (const float*)d_in[10];
    const float* cb1    = (const float*)d_in[11];
    const float* cW2    = (const float*)d_in[12];
    const float* cb2    = (const float*)d_in[13];
    const float* nW1    = (const float*)d_in[14];
    const float* nb1    = (const float*)d_in[15];
    const float* nW2    = (const float*)d_in[16];
    const float* nb2    = (const float*)d_in[17];
    const float* linW   = (const float*)d_in[18];
    const float* linb   = (const float*)d_in[19];
    float* out = (float*)d_out;

    cudaFuncSetAttribute(edge_kernel, cudaFuncAttributeMaxDynamicSharedMemorySize,
                         EDGE_SMEM_F * 4);
    cudaFuncSetAttribute(node_kernel, cudaFuncAttributeMaxDynamicSharedMemorySize,
                         NODE_SMEM_F * 4);
    cudaFuncSetAttribute(prenode_kernel, cudaFuncAttributeMaxDynamicSharedMemorySize,
                         PRE_SMEM_F * 4);

    {
        int total = NL * K1 * N1 + NL * N1;
        pad_kernel<<<(total + 255) / 256, 256>>>(eW1, eb1);
    }
    embed_kernel<<<(N_NODES * HID + 255) / 256, 256>>>(x, pos, embedW, embedb);

    const int egrid = (N_EDGES + ETILE - 1) / ETILE;
    const int ngrid = (N_NODES + 63) / 64;
    for (int l = 0; l < NL; l++) {
        prenode_kernel<<<ngrid, TPB, PRE_SMEM_F * 4>>>(l);
        edge_kernel<<<egrid, TPB, EDGE_SMEM_F * 4>>>(ei, eattr, eW2, eb2, cW1, cb1,
                                                     cW2, cb2, l);
        node_kernel<<<ngrid, TPB, NODE_SMEM_F * 4>>>(nW1, nb1, nW2, nb2, l);
    }
    final_kernel<<<(N_NODES * 32 + 255) / 256, 256>>>(linW, linb, out);
}